// round 1
// baseline (speedup 1.0000x reference)
#include <cuda_runtime.h>
#include <cuda_bf16.h>
#include <math.h>

// Problem constants
#define BB   2
#define NN   2048
#define MM   128
#define HH   16
#define DD   64
#define IND  1024
#define CTXD 768
#define ROWS (BB*NN)          // 4096
#define KVW  (2*HH*DD)        // 2048
#define KEXT 129              // 1 null + 128 ctx keys

// ---------------- scratch (static device globals; no allocation) -------------
__device__ float g_xn  [ROWS*IND];
__device__ float g_q   [ROWS*HH*DD];
__device__ float g_kv  [ROWS*KVW];
__device__ float g_kext[BB*KEXT*DD];
__device__ float g_vext[BB*KEXT*DD];
__device__ float g_attn[ROWS*HH*DD];
__device__ float g_proj[ROWS*IND];

// ---------------- block reduction helper -------------------------------------
__device__ __forceinline__ float block_reduce_sum(float v, float* sbuf) {
    __syncthreads();                       // protect sbuf reuse across calls
    int lane = threadIdx.x & 31, warp = threadIdx.x >> 5;
    #pragma unroll
    for (int o = 16; o; o >>= 1) v += __shfl_xor_sync(0xffffffffu, v, o);
    if (lane == 0) sbuf[warp] = v;
    __syncthreads();
    int nw = (blockDim.x + 31) >> 5;
    v = (threadIdx.x < nw) ? sbuf[threadIdx.x] : 0.0f;
    if (warp == 0) {
        #pragma unroll
        for (int o = 16; o; o >>= 1) v += __shfl_xor_sync(0xffffffffu, v, o);
        if (lane == 0) sbuf[0] = v;
    }
    __syncthreads();
    return sbuf[0];
}

// ---------------- layernorm (one block per row) -------------------------------
__global__ void ln_kernel(const float* __restrict__ in, float* __restrict__ out,
                          const float* __restrict__ g, const float* __restrict__ b,
                          int C) {
    __shared__ float sbuf[32];
    const float* x = in + (size_t)blockIdx.x * C;
    float s = 0.f, s2 = 0.f;
    for (int i = threadIdx.x; i < C; i += blockDim.x) {
        float v = x[i]; s += v; s2 += v * v;
    }
    s  = block_reduce_sum(s,  sbuf);
    s2 = block_reduce_sum(s2, sbuf);
    float mean = s / C;
    float rstd = rsqrtf(s2 / C - mean * mean + 1e-5f);
    float* o = out + (size_t)blockIdx.x * C;
    for (int i = threadIdx.x; i < C; i += blockDim.x)
        o[i] = (x[i] - mean) * rstd * g[i] + b[i];
}

// ---------------- ctx branch: LN(768) + GEMV(768x128) fused --------------------
// grid = B*M blocks, 256 threads
__global__ void ctx_kernel(const float* __restrict__ c_emb,
                           const float* __restrict__ g, const float* __restrict__ b,
                           const float* __restrict__ W,   // (768,128) row-major
                           const float* __restrict__ bctx,
                           float* __restrict__ kext, float* __restrict__ vext) {
    __shared__ float row[CTXD];
    __shared__ float sbuf[32];
    int rid = blockIdx.x;                 // 0..255
    int bb = rid >> 7, m = rid & 127;
    const float* x = c_emb + (size_t)rid * CTXD;
    float s = 0.f, s2 = 0.f;
    for (int i = threadIdx.x; i < CTXD; i += blockDim.x) {
        float v = x[i]; row[i] = v; s += v; s2 += v * v;
    }
    s  = block_reduce_sum(s,  sbuf);
    s2 = block_reduce_sum(s2, sbuf);
    float mean = s / CTXD;
    float rstd = rsqrtf(s2 / CTXD - mean * mean + 1e-5f);
    for (int i = threadIdx.x; i < CTXD; i += blockDim.x)
        row[i] = (row[i] - mean) * rstd * g[i] + b[i];
    __syncthreads();
    if (threadIdx.x < 128) {
        int j = threadIdx.x;
        float acc = bctx[j];
        #pragma unroll 8
        for (int d = 0; d < CTXD; d++) acc += row[d] * W[d * 128 + j];
        if (j < DD) kext[((size_t)bb * KEXT + m + 1) * DD + j] = acc;
        else        vext[((size_t)bb * KEXT + m + 1) * DD + (j - DD)] = acc;
    }
}

// ---------------- write null K/V rows -----------------------------------------
__global__ void null_kernel(const float* __restrict__ null_kv,
                            float* __restrict__ kext, float* __restrict__ vext) {
    int t = threadIdx.x;                  // 128 threads
    if (t < DD) {
        float v = null_kv[t];
        kext[0 * KEXT * DD + t] = v;
        kext[1 * KEXT * DD + t] = v;
    } else {
        int d = t - DD;
        float v = null_kv[DD + d];
        vext[0 * KEXT * DD + d] = v;
        vext[1 * KEXT * DD + d] = v;
    }
}

// ---------------- SGEMM: C(MxN) = A(MxK) x B(KxN), all row-major ----------------
// 128x128 tile, BK=8, 256 threads, 8x8 micro-tile
#define GBM 128
#define GBN 128
#define GBK 8
__global__ __launch_bounds__(256) void sgemm_kernel(
        const float* __restrict__ A, const float* __restrict__ B,
        float* __restrict__ C, int M, int N, int K) {
    __shared__ float As[GBK][GBM];
    __shared__ float Bs[GBK][GBN];
    int tid = threadIdx.x;
    int tx = tid & 15, ty = tid >> 4;
    int aRow = tid >> 1, aCol = (tid & 1) * 4;
    int bRow = tid >> 5, bCol = (tid & 31) * 4;
    const float* Ab = A + (size_t)(blockIdx.y * GBM) * K;
    const float* Bb = B + blockIdx.x * GBN;
    float acc[8][8];
    #pragma unroll
    for (int i = 0; i < 8; i++)
        #pragma unroll
        for (int j = 0; j < 8; j++) acc[i][j] = 0.f;

    for (int k0 = 0; k0 < K; k0 += GBK) {
        float4 av = *(const float4*)(Ab + (size_t)aRow * K + k0 + aCol);
        As[aCol + 0][aRow] = av.x; As[aCol + 1][aRow] = av.y;
        As[aCol + 2][aRow] = av.z; As[aCol + 3][aRow] = av.w;
        float4 bv = *(const float4*)(Bb + (size_t)(k0 + bRow) * N + bCol);
        *(float4*)&Bs[bRow][bCol] = bv;
        __syncthreads();
        #pragma unroll
        for (int k = 0; k < GBK; k++) {
            float a[8], b[8];
            #pragma unroll
            for (int i = 0; i < 8; i++) a[i] = As[k][ty * 8 + i];
            #pragma unroll
            for (int j = 0; j < 8; j++) b[j] = Bs[k][tx * 8 + j];
            #pragma unroll
            for (int i = 0; i < 8; i++)
                #pragma unroll
                for (int j = 0; j < 8; j++) acc[i][j] += a[i] * b[j];
        }
        __syncthreads();
    }
    #pragma unroll
    for (int i = 0; i < 8; i++) {
        float* cr = C + (size_t)(blockIdx.y * GBM + ty * 8 + i) * N + blockIdx.x * GBN + tx * 8;
        float4 v0 = make_float4(acc[i][0], acc[i][1], acc[i][2], acc[i][3]);
        float4 v1 = make_float4(acc[i][4], acc[i][5], acc[i][6], acc[i][7]);
        *(float4*)cr = v0;
        *(float4*)(cr + 4) = v1;
    }
}

// ---------------- flash attention: 1 thread = 1 query --------------------------
// grid (N/128, H, B), block 128. K/V tiles of 64 keys staged in smem.
#define KTILE 64
__global__ __launch_bounds__(128) void attn_kernel(
        const float* __restrict__ qb, const float* __restrict__ kvb,
        const float* __restrict__ kext, const float* __restrict__ vext,
        float* __restrict__ outb) {
    __shared__ float Ks[KTILE][DD];
    __shared__ float Vs[KTILE][DD];
    int b = blockIdx.z, h = blockIdx.y;
    int tid = threadIdx.x;
    int qidx = blockIdx.x * 128 + tid;
    const float scale = 0.125f;           // D^-0.5, D=64

    float qreg[DD];
    {
        const float* qrow = qb + ((size_t)(b * NN + qidx)) * (HH * DD) + h * DD;
        #pragma unroll
        for (int i = 0; i < 16; i++) {
            float4 v = *(const float4*)(qrow + i * 4);
            qreg[i * 4 + 0] = v.x; qreg[i * 4 + 1] = v.y;
            qreg[i * 4 + 2] = v.z; qreg[i * 4 + 3] = v.w;
        }
    }
    float mrun = -INFINITY, lrun = 0.f;
    float acc[DD];
    #pragma unroll
    for (int d = 0; d < DD; d++) acc[d] = 0.f;

    // ---- self keys: 2048, tiles of 64 ----
    for (int k0 = 0; k0 < NN; k0 += KTILE) {
        __syncthreads();
        #pragma unroll
        for (int i = 0; i < 8; i++) {
            int idx = tid + i * 128;       // 0..1023
            int j = idx >> 4, c = (idx & 15) << 2;
            const float* base = kvb + ((size_t)(b * NN + k0 + j)) * KVW + h * DD + c;
            *(float4*)&Ks[j][c] = *(const float4*)base;
            *(float4*)&Vs[j][c] = *(const float4*)(base + HH * DD);
        }
        __syncthreads();
        for (int j = 0; j < KTILE; j++) {
            float sx = 0.f, sy = 0.f, sz = 0.f, sw = 0.f;
            #pragma unroll
            for (int i = 0; i < 16; i++) {
                float4 kv4 = *(const float4*)&Ks[j][i * 4];
                sx += qreg[i * 4 + 0] * kv4.x; sy += qreg[i * 4 + 1] * kv4.y;
                sz += qreg[i * 4 + 2] * kv4.z; sw += qreg[i * 4 + 3] * kv4.w;
            }
            float s = (sx + sy + sz + sw) * scale;
            if (s > mrun) {
                float f = __expf(mrun - s);
                lrun = lrun * f + 1.f;
                #pragma unroll
                for (int d = 0; d < DD; d++) acc[d] = acc[d] * f + Vs[j][d];
                mrun = s;
            } else {
                float p = __expf(s - mrun);
                lrun += p;
                #pragma unroll
                for (int d = 0; d < DD; d++) acc[d] += p * Vs[j][d];
            }
        }
    }

    // ---- ctx keys: 129 (incl. null), tiles of 64 ----
    for (int k0 = 0; k0 < KEXT; k0 += KTILE) {
        int cnt = min(KTILE, KEXT - k0);
        __syncthreads();
        #pragma unroll
        for (int i = 0; i < 8; i++) {
            int idx = tid + i * 128;
            int j = idx >> 4, c = (idx & 15) << 2;
            if (j < cnt) {
                size_t off = ((size_t)b * KEXT + k0 + j) * DD + c;
                *(float4*)&Ks[j][c] = *(const float4*)(kext + off);
                *(float4*)&Vs[j][c] = *(const float4*)(vext + off);
            }
        }
        __syncthreads();
        for (int j = 0; j < cnt; j++) {
            float sx = 0.f, sy = 0.f, sz = 0.f, sw = 0.f;
            #pragma unroll
            for (int i = 0; i < 16; i++) {
                float4 kv4 = *(const float4*)&Ks[j][i * 4];
                sx += qreg[i * 4 + 0] * kv4.x; sy += qreg[i * 4 + 1] * kv4.y;
                sz += qreg[i * 4 + 2] * kv4.z; sw += qreg[i * 4 + 3] * kv4.w;
            }
            float s = (sx + sy + sz + sw) * scale;
            if (s > mrun) {
                float f = __expf(mrun - s);
                lrun = lrun * f + 1.f;
                #pragma unroll
                for (int d = 0; d < DD; d++) acc[d] = acc[d] * f + Vs[j][d];
                mrun = s;
            } else {
                float p = __expf(s - mrun);
                lrun += p;
                #pragma unroll
                for (int d = 0; d < DD; d++) acc[d] += p * Vs[j][d];
            }
        }
    }

    float inv = 1.f / lrun;
    float* orow = outb + ((size_t)(b * NN + qidx)) * (HH * DD) + h * DD;
    #pragma unroll
    for (int d = 0; d < DD; d += 4) {
        float4 o = make_float4(acc[d] * inv, acc[d + 1] * inv, acc[d + 2] * inv, acc[d + 3] * inv);
        *(float4*)(orow + d) = o;
    }
}

// ---------------- host launcher ------------------------------------------------
extern "C" void kernel_launch(void* const* d_in, const int* in_sizes, int n_in,
                              void* d_out, int out_size) {
    const float* x        = (const float*)d_in[0];
    const float* c_emb    = (const float*)d_in[1];
    const float* ln_g     = (const float*)d_in[2];
    const float* ln_b     = (const float*)d_in[3];
    const float* ctx_ln_g = (const float*)d_in[4];
    const float* ctx_ln_b = (const float*)d_in[5];
    const float* W_ctx    = (const float*)d_in[6];
    const float* b_ctx    = (const float*)d_in[7];
    const float* W_q      = (const float*)d_in[8];
    const float* W_kv     = (const float*)d_in[9];
    const float* null_kv  = (const float*)d_in[10];
    const float* W_out    = (const float*)d_in[11];
    const float* out_ln_g = (const float*)d_in[12];
    const float* out_ln_b = (const float*)d_in[13];
    float* out = (float*)d_out;

    float *xn, *qb, *kvb, *kext, *vext, *attn, *proj;
    cudaGetSymbolAddress((void**)&xn,   g_xn);
    cudaGetSymbolAddress((void**)&qb,   g_q);
    cudaGetSymbolAddress((void**)&kvb,  g_kv);
    cudaGetSymbolAddress((void**)&kext, g_kext);
    cudaGetSymbolAddress((void**)&vext, g_vext);
    cudaGetSymbolAddress((void**)&attn, g_attn);
    cudaGetSymbolAddress((void**)&proj, g_proj);

    // 1. LN(x)
    ln_kernel<<<ROWS, 256>>>(x, xn, ln_g, ln_b, IND);
    // 2. ctx branch (independent of 1)
    ctx_kernel<<<BB * MM, 256>>>(c_emb, ctx_ln_g, ctx_ln_b, W_ctx, b_ctx, kext, vext);
    null_kernel<<<1, 128>>>(null_kv, kext, vext);
    // 3. Q and KV GEMMs
    sgemm_kernel<<<dim3((HH * DD) / GBN, ROWS / GBM), 256>>>(xn, W_q,  qb,  ROWS, HH * DD, IND);
    sgemm_kernel<<<dim3(KVW / GBN,       ROWS / GBM), 256>>>(xn, W_kv, kvb, ROWS, KVW,     IND);
    // 4. attention
    attn_kernel<<<dim3(NN / 128, HH, BB), 128>>>(qb, kvb, kext, vext, attn);
    // 5. output projection
    sgemm_kernel<<<dim3(IND / GBN, ROWS / GBM), 256>>>(attn, W_out, proj, ROWS, IND, IND);
    // 6. final LN -> d_out
    ln_kernel<<<ROWS, 256>>>(proj, out, out_ln_g, out_ln_b, IND);
}